// round 7
// baseline (speedup 1.0000x reference)
#include <cuda_runtime.h>
#include <cuda_fp16.h>

#define N_NODES 100000
#define N_EDGES 1600000
#define D       128
#define LN_EPS  1e-5f

// lookback scan config
#define TILE_THREADS 256
#define ITEMS        16
#define SCAN_TILE    (TILE_THREADS * ITEMS)                  // 4096
#define N_TILES      ((N_NODES + SCAN_TILE - 1) / SCAN_TILE) // 25

// ------- scratch (device globals; zero-initialized at load) -------
__device__ int    g_cnt[N_NODES];          // degrees; reset by layer0 epilogue
__device__ int    g_rowptr[N_NODES + 1];   // exclusive prefix; [N] set by scatter
__device__ int    g_cursor[N_NODES];       // scan writes prefix; scatter consumes
__device__ int    g_tstate[N_TILES];       // reset by scatter (post-scan)
__device__ int    g_ticket;                // reset by scatter (post-scan)
__device__ int2   g_edge[N_EDGES];         // (src, val) in CSR order
__device__ __half g_xh[N_NODES * D];       // fp16 copy of x   (25.6 MB)
__device__ __half g_h[N_NODES * D];        // fp16 layer-0 out (25.6 MB)

// ---------------- packed f32x2 helpers (sm_103a FFMA2) ----------------
__device__ __forceinline__ unsigned long long pk2(float x, float y) {
    unsigned long long r;
    asm("mov.b64 %0, {%1, %2};" : "=l"(r) : "f"(x), "f"(y));
    return r;
}
__device__ __forceinline__ void upk2(unsigned long long p, float& x, float& y) {
    asm("mov.b64 {%0, %1}, %2;" : "=f"(x), "=f"(y) : "l"(p));
}
__device__ __forceinline__ void ffma2(unsigned long long& a,
                                      unsigned long long x,
                                      unsigned long long v) {
    asm("fma.rn.f32x2 %0, %1, %2, %0;" : "+l"(a) : "l"(x), "l"(v));
}

// ---------------------------------------------------------------
// fused: fp32->fp16 conversion of x  +  degree histogram
// (atomic results discarded -> REDG no-return; overlaps DRAM stream)
// ---------------------------------------------------------------
__global__ void k_cvt_hist(const float* __restrict__ x,
                           const int* __restrict__ dst) {
    int tid = blockIdx.x * blockDim.x + threadIdx.x;
    int gsz = gridDim.x * blockDim.x;

    const float4* x4 = (const float4*)x;
    uint2* o2 = (uint2*)g_xh;
    for (int i = tid; i < N_NODES * D / 4; i += gsz) {
        float4 v = x4[i];
        __half2 lo = __floats2half2_rn(v.x, v.y);
        __half2 hi = __floats2half2_rn(v.z, v.w);
        uint2 p;
        p.x = *(unsigned int*)&lo;
        p.y = *(unsigned int*)&hi;
        o2[i] = p;
    }

    const int4* d4 = (const int4*)dst;
    for (int i = tid; i < N_EDGES / 4; i += gsz) {
        int4 d = d4[i];
        atomicAdd(&g_cnt[d.x], 1);
        atomicAdd(&g_cnt[d.y], 1);
        atomicAdd(&g_cnt[d.z], 1);
        atomicAdd(&g_cnt[d.w], 1);
    }
}

// ---------------------------------------------------------------
// single-pass exclusive scan (decoupled lookback): g_cnt -> g_rowptr
// ALSO writes the same prefix into g_cursor (scatter's atomic base)
// ---------------------------------------------------------------
__global__ void __launch_bounds__(TILE_THREADS) k_scan() {
    __shared__ int sh_warp[TILE_THREADS / 32];
    __shared__ int sh_prev;
    __shared__ int sh_tile;

    int t = threadIdx.x;
    if (t == 0) sh_tile = atomicAdd(&g_ticket, 1);
    __syncthreads();
    int tile = sh_tile;
    int base = tile * SCAN_TILE + t * ITEMS;

    int v[ITEMS];
    #pragma unroll
    for (int i = 0; i < ITEMS; i += 4) {
        int idx = base + i;
        int4 c;
        if (idx + 3 < N_NODES) {
            c = *(const int4*)&g_cnt[idx];
        } else {
            c.x = (idx     < N_NODES) ? g_cnt[idx]     : 0;
            c.y = (idx + 1 < N_NODES) ? g_cnt[idx + 1] : 0;
            c.z = (idx + 2 < N_NODES) ? g_cnt[idx + 2] : 0;
            c.w = (idx + 3 < N_NODES) ? g_cnt[idx + 3] : 0;
        }
        v[i] = c.x; v[i + 1] = c.y; v[i + 2] = c.z; v[i + 3] = c.w;
    }
    #pragma unroll
    for (int i = 1; i < ITEMS; i++) v[i] += v[i - 1];

    int tot = v[ITEMS - 1];
    int lane = t & 31, wid = t >> 5;
    int s = tot;
    #pragma unroll
    for (int o = 1; o < 32; o <<= 1) {
        int n = __shfl_up_sync(0xffffffffu, s, o);
        if (lane >= o) s += n;
    }
    if (lane == 31) sh_warp[wid] = s;
    __syncthreads();
    if (wid == 0) {
        int ws = (lane < TILE_THREADS / 32) ? sh_warp[lane] : 0;
        #pragma unroll
        for (int o = 1; o < TILE_THREADS / 32; o <<= 1) {
            int n = __shfl_up_sync(0xffffffffu, ws, o);
            if (lane >= o) ws += n;
        }
        if (lane < TILE_THREADS / 32) sh_warp[lane] = ws;
    }
    __syncthreads();
    int thr_excl  = (wid > 0 ? sh_warp[wid - 1] : 0) + (s - tot);
    int block_tot = sh_warp[TILE_THREADS / 32 - 1];

    if (t == 0) {
        if (tile == 0) {
            __threadfence();
            atomicExch(&g_tstate[0], (block_tot << 2) | 2);
            sh_prev = 0;
        } else {
            __threadfence();
            atomicExch(&g_tstate[tile], (block_tot << 2) | 1);
            int prev = 0;
            int j = tile - 1;
            while (true) {
                int st = atomicAdd(&g_tstate[j], 0);
                int f = st & 3;
                if (f == 2) { prev += st >> 2; break; }
                if (f == 1) { prev += st >> 2; j--; }
            }
            __threadfence();
            atomicExch(&g_tstate[tile], ((prev + block_tot) << 2) | 2);
            sh_prev = prev;
        }
    }
    __syncthreads();
    int excl = sh_prev + thr_excl;

    #pragma unroll
    for (int i = 0; i < ITEMS; i += 4) {
        int idx = base + i;
        int4 o;
        o.x = excl + (i > 0 ? v[i - 1] : 0);
        o.y = excl + v[i];
        o.z = excl + v[i + 1];
        o.w = excl + v[i + 2];
        if (idx + 3 < N_NODES) {
            *(int4*)&g_rowptr[idx] = o;
            *(int4*)&g_cursor[idx] = o;
        } else {
            if (idx     < N_NODES) { g_rowptr[idx]     = o.x; g_cursor[idx]     = o.x; }
            if (idx + 1 < N_NODES) { g_rowptr[idx + 1] = o.y; g_cursor[idx + 1] = o.y; }
            if (idx + 2 < N_NODES) { g_rowptr[idx + 2] = o.z; g_cursor[idx + 2] = o.z; }
            if (idx + 3 < N_NODES) { g_rowptr[idx + 3] = o.w; g_cursor[idx + 3] = o.w; }
        }
    }
}

// ---------------------------------------------------------------
// scatter: p = atomicAdd(&cursor[d], 1) gives the absolute slot.
// Also resets scan state for next replay.
// ---------------------------------------------------------------
__global__ void k_scatter(const int* __restrict__ src,
                          const int* __restrict__ dst,
                          const float* __restrict__ val) {
    int e = blockIdx.x * blockDim.x + threadIdx.x;
    if (e < N_TILES) g_tstate[e] = 0;                 // post-scan reset
    if (e == N_TILES)     g_ticket = 0;
    if (e == N_TILES + 1) g_rowptr[N_NODES] = N_EDGES;
    if (e >= N_EDGES) return;
    int   d = dst[e];
    int   s = src[e];
    float v = val[e];
    int p = atomicAdd(&g_cursor[d], 1);
    g_edge[p] = make_int2(s, __float_as_int(v));
}

// ---------------------------------------------------------------
// fused gather(fp16)-aggregate(fp32) + diag-scale + LayerNorm (+ReLU)
// HALF-WARP layout: 16 lanes cover one 256B row (uint4 = 8 halfs/lane);
// the two half-warps process two edges concurrently. Packed FFMA2 math.
// ---------------------------------------------------------------
template <bool RELU, bool OUT_HALF, bool RESET_CNT>
__device__ __forceinline__ void agg_node(const __half* __restrict__ in,
                                         const float* __restrict__ w,
                                         const float* __restrict__ gam,
                                         const float* __restrict__ bet,
                                         void* __restrict__ out) {
    int node = (blockIdx.x * blockDim.x + threadIdx.x) >> 5;
    int lane = threadIdx.x & 31;
    if (node >= N_NODES) return;
    int hw = lane >> 4;        // which edge of the pair
    int sl = lane & 15;        // position within the row (8 halfs each)

    int beg = g_rowptr[node];
    int end = g_rowptr[node + 1];
    if (RESET_CNT && lane == 0) g_cnt[node] = 0;   // state reset for next replay

    // 4 packed f32x2 accumulators = features [8sl, 8sl+8)
    unsigned long long a0 = 0, a1 = 0, a2 = 0, a3 = 0;
    const uint4* in4 = (const uint4*)in;           // 16 uint4 per row

    int e = beg;

    // align to even edge index (single-edge step: hw=1 contributes 0)
    if ((e & 1) && e < end) {
        int2 ed = g_edge[e];
        float v = hw ? 0.f : __int_as_float(ed.y);
        uint4 X = in4[ed.x * 16 + sl];
        unsigned long long vv = pk2(v, v);
        float2 f0 = __half22float2(*(__half2*)&X.x);
        float2 f1 = __half22float2(*(__half2*)&X.y);
        float2 f2 = __half22float2(*(__half2*)&X.z);
        float2 f3 = __half22float2(*(__half2*)&X.w);
        ffma2(a0, pk2(f0.x, f0.y), vv);
        ffma2(a1, pk2(f1.x, f1.y), vv);
        ffma2(a2, pk2(f2.x, f2.y), vv);
        ffma2(a3, pk2(f3.x, f3.y), vv);
        e++;
    }

    // main: 4 edges per iteration (2 per half-warp), 2 row loads in flight
    for (; e + 4 <= end; e += 4) {
        int4 mA = *(const int4*)&g_edge[e];        // edges e, e+1
        int4 mB = *(const int4*)&g_edge[e + 2];    // edges e+2, e+3
        int   sA = hw ? mA.z : mA.x;
        int   sB = hw ? mB.z : mB.x;
        float vA = __int_as_float(hw ? mA.w : mA.y);
        float vB = __int_as_float(hw ? mB.w : mB.y);
        uint4 XA = in4[sA * 16 + sl];
        uint4 XB = in4[sB * 16 + sl];
        unsigned long long vvA = pk2(vA, vA);
        unsigned long long vvB = pk2(vB, vB);
        {
            float2 f0 = __half22float2(*(__half2*)&XA.x);
            float2 f1 = __half22float2(*(__half2*)&XA.y);
            float2 f2 = __half22float2(*(__half2*)&XA.z);
            float2 f3 = __half22float2(*(__half2*)&XA.w);
            ffma2(a0, pk2(f0.x, f0.y), vvA);
            ffma2(a1, pk2(f1.x, f1.y), vvA);
            ffma2(a2, pk2(f2.x, f2.y), vvA);
            ffma2(a3, pk2(f3.x, f3.y), vvA);
        }
        {
            float2 f0 = __half22float2(*(__half2*)&XB.x);
            float2 f1 = __half22float2(*(__half2*)&XB.y);
            float2 f2 = __half22float2(*(__half2*)&XB.z);
            float2 f3 = __half22float2(*(__half2*)&XB.w);
            ffma2(a0, pk2(f0.x, f0.y), vvB);
            ffma2(a1, pk2(f1.x, f1.y), vvB);
            ffma2(a2, pk2(f2.x, f2.y), vvB);
            ffma2(a3, pk2(f3.x, f3.y), vvB);
        }
    }

    // 2-edge step
    if (e + 2 <= end) {
        int4 m = *(const int4*)&g_edge[e];
        int   s = hw ? m.z : m.x;
        float v = __int_as_float(hw ? m.w : m.y);
        uint4 X = in4[s * 16 + sl];
        unsigned long long vv = pk2(v, v);
        float2 f0 = __half22float2(*(__half2*)&X.x);
        float2 f1 = __half22float2(*(__half2*)&X.y);
        float2 f2 = __half22float2(*(__half2*)&X.z);
        float2 f3 = __half22float2(*(__half2*)&X.w);
        ffma2(a0, pk2(f0.x, f0.y), vv);
        ffma2(a1, pk2(f1.x, f1.y), vv);
        ffma2(a2, pk2(f2.x, f2.y), vv);
        ffma2(a3, pk2(f3.x, f3.y), vv);
        e += 2;
    }

    // final single edge
    if (e < end) {
        int2 ed = g_edge[e];
        float v = hw ? 0.f : __int_as_float(ed.y);
        uint4 X = in4[ed.x * 16 + sl];
        unsigned long long vv = pk2(v, v);
        float2 f0 = __half22float2(*(__half2*)&X.x);
        float2 f1 = __half22float2(*(__half2*)&X.y);
        float2 f2 = __half22float2(*(__half2*)&X.z);
        float2 f3 = __half22float2(*(__half2*)&X.w);
        ffma2(a0, pk2(f0.x, f0.y), vv);
        ffma2(a1, pk2(f1.x, f1.y), vv);
        ffma2(a2, pk2(f2.x, f2.y), vv);
        ffma2(a3, pk2(f3.x, f3.y), vv);
    }

    // unpack, combine half-warps (each lane ends with full sums for its 8 feats)
    float t[8];
    upk2(a0, t[0], t[1]);
    upk2(a1, t[2], t[3]);
    upk2(a2, t[4], t[5]);
    upk2(a3, t[6], t[7]);
    #pragma unroll
    for (int i = 0; i < 8; i++)
        t[i] += __shfl_xor_sync(0xffffffffu, t[i], 16);

    // diag transform: t *= w  (features [8sl, 8sl+8))
    float4 wA = ((const float4*)w)[2 * sl];
    float4 wB = ((const float4*)w)[2 * sl + 1];
    t[0] *= wA.x; t[1] *= wA.y; t[2] *= wA.z; t[3] *= wA.w;
    t[4] *= wB.x; t[5] *= wB.y; t[6] *= wB.z; t[7] *= wB.w;

    // LayerNorm sums (each feature appears in BOTH half-warps -> totals are 2x)
    float sm = 0.f, sq = 0.f;
    #pragma unroll
    for (int i = 0; i < 8; i++) { sm += t[i]; sq += t[i] * t[i]; }
    #pragma unroll
    for (int o = 16; o; o >>= 1) {
        sm += __shfl_xor_sync(0xffffffffu, sm, o);
        sq += __shfl_xor_sync(0xffffffffu, sq, o);
    }
    float mu  = sm * (1.f / (2 * D));
    float var = sq * (1.f / (2 * D)) - mu * mu;
    float rs  = rsqrtf(var + LN_EPS);

    // each lane writes 4 features: [8sl + 4hw, +4)  -> chunk index 2sl+hw
    int ci = 2 * sl + hw;
    float4 g4 = ((const float4*)gam)[ci];
    float4 b4 = ((const float4*)bet)[ci];
    float u0 = t[4 * hw + 0], u1 = t[4 * hw + 1];
    float u2 = t[4 * hw + 2], u3 = t[4 * hw + 3];
    float4 o4;
    o4.x = fmaf((u0 - mu) * rs, g4.x, b4.x);
    o4.y = fmaf((u1 - mu) * rs, g4.y, b4.y);
    o4.z = fmaf((u2 - mu) * rs, g4.z, b4.z);
    o4.w = fmaf((u3 - mu) * rs, g4.w, b4.w);
    if (RELU) {
        o4.x = fmaxf(o4.x, 0.f); o4.y = fmaxf(o4.y, 0.f);
        o4.z = fmaxf(o4.z, 0.f); o4.w = fmaxf(o4.w, 0.f);
    }

    if (OUT_HALF) {
        __half2 lo = __floats2half2_rn(o4.x, o4.y);
        __half2 hi = __floats2half2_rn(o4.z, o4.w);
        uint2 p;
        p.x = *(unsigned int*)&lo;
        p.y = *(unsigned int*)&hi;
        ((uint2*)out)[node * 32 + ci] = p;
    } else {
        ((float4*)out)[node * 32 + ci] = o4;
    }
}

__global__ void k_layer0(const float* __restrict__ w,
                         const float* __restrict__ gam,
                         const float* __restrict__ bet) {
    agg_node<true, true, true>(g_xh, w, gam, bet, (void*)g_h);
}

__global__ void k_layer1(const float* __restrict__ w,
                         const float* __restrict__ gam,
                         const float* __restrict__ bet,
                         float* __restrict__ out) {
    agg_node<false, false, false>(g_h, w, gam, bet, (void*)out);
}

// ---------------------------------------------------------------
extern "C" void kernel_launch(void* const* d_in, const int* in_sizes, int n_in,
                              void* d_out, int out_size) {
    const float* x     = (const float*)d_in[0];
    const int*   esrc  = (const int*)  d_in[1];
    const int*   edst  = (const int*)  d_in[2];
    const float* eval_ = (const float*)d_in[3];
    const float* w1    = (const float*)d_in[4];
    const float* w2    = (const float*)d_in[5];
    const float* ln1g  = (const float*)d_in[6];
    const float* ln1b  = (const float*)d_in[7];
    const float* ln2g  = (const float*)d_in[8];
    const float* ln2b  = (const float*)d_in[9];
    float* out = (float*)d_out;

    k_cvt_hist<<<1024, 256>>>(x, edst);
    k_scan<<<N_TILES, TILE_THREADS>>>();
    k_scatter<<<(N_EDGES + 255) / 256, 256>>>(esrc, edst, eval_);

    int blocks = (N_NODES * 32 + 255) / 256;
    k_layer0<<<blocks, 256>>>(w1, ln1g, ln1b);
    k_layer1<<<blocks, 256>>>(w2, ln2g, ln2b, out);
}

// round 8
// speedup vs baseline: 1.0251x; 1.0251x over previous
#include <cuda_runtime.h>
#include <cuda_fp16.h>

#define N_NODES 100000
#define N_EDGES 1600000
#define D       128
#define LN_EPS  1e-5f

// lookback scan config
#define TILE_THREADS 256
#define ITEMS        16
#define SCAN_TILE    (TILE_THREADS * ITEMS)                  // 4096
#define N_TILES      ((N_NODES + SCAN_TILE - 1) / SCAN_TILE) // 25

// ------- scratch (device globals; zero-initialized at load) -------
__device__ int    g_cnt[N_NODES];          // degrees; reset by layer0 epilogue
__device__ int    g_rowptr[N_NODES + 1];   // exclusive prefix; [N] set by scatter
__device__ int    g_cursor[N_NODES];       // scan writes prefix; scatter consumes
__device__ int    g_tstate[N_TILES];       // reset by scatter (post-scan)
__device__ int    g_ticket;                // reset by scatter (post-scan)
__device__ int2   g_edge[N_EDGES];         // (src, val) in CSR order
__device__ __half g_xh[N_NODES * D];       // fp16 copy of x   (25.6 MB)
__device__ __half g_h[N_NODES * D];        // fp16 layer-0 out (25.6 MB)

// ---------------------------------------------------------------
// fused: fp32->fp16 conversion of x  +  degree histogram
// (atomic results discarded -> REDG no-return; overlaps DRAM stream)
// ---------------------------------------------------------------
__global__ void k_cvt_hist(const float* __restrict__ x,
                           const int* __restrict__ dst) {
    int tid = blockIdx.x * blockDim.x + threadIdx.x;
    int gsz = gridDim.x * blockDim.x;

    const float4* x4 = (const float4*)x;
    uint2* o2 = (uint2*)g_xh;
    for (int i = tid; i < N_NODES * D / 4; i += gsz) {
        float4 v = x4[i];
        __half2 lo = __floats2half2_rn(v.x, v.y);
        __half2 hi = __floats2half2_rn(v.z, v.w);
        uint2 p;
        p.x = *(unsigned int*)&lo;
        p.y = *(unsigned int*)&hi;
        o2[i] = p;
    }

    const int4* d4 = (const int4*)dst;
    for (int i = tid; i < N_EDGES / 4; i += gsz) {
        int4 d = d4[i];
        atomicAdd(&g_cnt[d.x], 1);
        atomicAdd(&g_cnt[d.y], 1);
        atomicAdd(&g_cnt[d.z], 1);
        atomicAdd(&g_cnt[d.w], 1);
    }
}

// ---------------------------------------------------------------
// single-pass exclusive scan (decoupled lookback): g_cnt -> g_rowptr
// ALSO writes the same prefix into g_cursor (scatter's atomic base)
// ---------------------------------------------------------------
__global__ void __launch_bounds__(TILE_THREADS) k_scan() {
    __shared__ int sh_warp[TILE_THREADS / 32];
    __shared__ int sh_prev;
    __shared__ int sh_tile;

    int t = threadIdx.x;
    if (t == 0) sh_tile = atomicAdd(&g_ticket, 1);
    __syncthreads();
    int tile = sh_tile;
    int base = tile * SCAN_TILE + t * ITEMS;

    int v[ITEMS];
    #pragma unroll
    for (int i = 0; i < ITEMS; i += 4) {
        int idx = base + i;
        int4 c;
        if (idx + 3 < N_NODES) {
            c = *(const int4*)&g_cnt[idx];
        } else {
            c.x = (idx     < N_NODES) ? g_cnt[idx]     : 0;
            c.y = (idx + 1 < N_NODES) ? g_cnt[idx + 1] : 0;
            c.z = (idx + 2 < N_NODES) ? g_cnt[idx + 2] : 0;
            c.w = (idx + 3 < N_NODES) ? g_cnt[idx + 3] : 0;
        }
        v[i] = c.x; v[i + 1] = c.y; v[i + 2] = c.z; v[i + 3] = c.w;
    }
    #pragma unroll
    for (int i = 1; i < ITEMS; i++) v[i] += v[i - 1];

    int tot = v[ITEMS - 1];
    int lane = t & 31, wid = t >> 5;
    int s = tot;
    #pragma unroll
    for (int o = 1; o < 32; o <<= 1) {
        int n = __shfl_up_sync(0xffffffffu, s, o);
        if (lane >= o) s += n;
    }
    if (lane == 31) sh_warp[wid] = s;
    __syncthreads();
    if (wid == 0) {
        int ws = (lane < TILE_THREADS / 32) ? sh_warp[lane] : 0;
        #pragma unroll
        for (int o = 1; o < TILE_THREADS / 32; o <<= 1) {
            int n = __shfl_up_sync(0xffffffffu, ws, o);
            if (lane >= o) ws += n;
        }
        if (lane < TILE_THREADS / 32) sh_warp[lane] = ws;
    }
    __syncthreads();
    int thr_excl  = (wid > 0 ? sh_warp[wid - 1] : 0) + (s - tot);
    int block_tot = sh_warp[TILE_THREADS / 32 - 1];

    if (t == 0) {
        if (tile == 0) {
            __threadfence();
            atomicExch(&g_tstate[0], (block_tot << 2) | 2);
            sh_prev = 0;
        } else {
            __threadfence();
            atomicExch(&g_tstate[tile], (block_tot << 2) | 1);
            int prev = 0;
            int j = tile - 1;
            while (true) {
                int st = atomicAdd(&g_tstate[j], 0);
                int f = st & 3;
                if (f == 2) { prev += st >> 2; break; }
                if (f == 1) { prev += st >> 2; j--; }
            }
            __threadfence();
            atomicExch(&g_tstate[tile], ((prev + block_tot) << 2) | 2);
            sh_prev = prev;
        }
    }
    __syncthreads();
    int excl = sh_prev + thr_excl;

    #pragma unroll
    for (int i = 0; i < ITEMS; i += 4) {
        int idx = base + i;
        int4 o;
        o.x = excl + (i > 0 ? v[i - 1] : 0);
        o.y = excl + v[i];
        o.z = excl + v[i + 1];
        o.w = excl + v[i + 2];
        if (idx + 3 < N_NODES) {
            *(int4*)&g_rowptr[idx] = o;
            *(int4*)&g_cursor[idx] = o;
        } else {
            if (idx     < N_NODES) { g_rowptr[idx]     = o.x; g_cursor[idx]     = o.x; }
            if (idx + 1 < N_NODES) { g_rowptr[idx + 1] = o.y; g_cursor[idx + 1] = o.y; }
            if (idx + 2 < N_NODES) { g_rowptr[idx + 2] = o.z; g_cursor[idx + 2] = o.z; }
            if (idx + 3 < N_NODES) { g_rowptr[idx + 3] = o.w; g_cursor[idx + 3] = o.w; }
        }
    }
}

// ---------------------------------------------------------------
// scatter: 4 edges per thread, independent atomics (MLP=4).
// p = atomicAdd(&cursor[d], 1) gives the absolute CSR slot.
// Also resets scan state for next replay.
// ---------------------------------------------------------------
__global__ void k_scatter(const int* __restrict__ src,
                          const int* __restrict__ dst,
                          const float* __restrict__ val) {
    int i = blockIdx.x * blockDim.x + threadIdx.x;
    if (i < N_TILES) g_tstate[i] = 0;                 // post-scan reset
    if (i == N_TILES)     g_ticket = 0;
    if (i == N_TILES + 1) g_rowptr[N_NODES] = N_EDGES;
    if (i >= N_EDGES / 4) return;
    int4   s = ((const int4*)src)[i];
    int4   d = ((const int4*)dst)[i];
    float4 v = ((const float4*)val)[i];
    int p0 = atomicAdd(&g_cursor[d.x], 1);
    int p1 = atomicAdd(&g_cursor[d.y], 1);
    int p2 = atomicAdd(&g_cursor[d.z], 1);
    int p3 = atomicAdd(&g_cursor[d.w], 1);
    g_edge[p0] = make_int2(s.x, __float_as_int(v.x));
    g_edge[p1] = make_int2(s.y, __float_as_int(v.y));
    g_edge[p2] = make_int2(s.z, __float_as_int(v.z));
    g_edge[p3] = make_int2(s.w, __float_as_int(v.w));
}

// ---------------------------------------------------------------
// fused gather(fp16)-aggregate(fp32) + diag-scale + LayerNorm (+ReLU)
// one warp per node; lane l owns features [4l, 4l+4)   (R6 form — frozen)
// ---------------------------------------------------------------
__device__ __forceinline__ float4 acc_row(float4 acc, uint2 u, float v) {
    float2 flo = __half22float2(*(__half2*)&u.x);
    float2 fhi = __half22float2(*(__half2*)&u.y);
    acc.x = fmaf(v, flo.x, acc.x);
    acc.y = fmaf(v, flo.y, acc.y);
    acc.z = fmaf(v, fhi.x, acc.z);
    acc.w = fmaf(v, fhi.y, acc.w);
    return acc;
}

template <bool RELU, bool OUT_HALF, bool RESET_CNT>
__device__ __forceinline__ void agg_node(const __half* __restrict__ in,
                                         const float* __restrict__ w,
                                         const float* __restrict__ gam,
                                         const float* __restrict__ bet,
                                         void* __restrict__ out) {
    int node = (blockIdx.x * blockDim.x + threadIdx.x) >> 5;
    int lane = threadIdx.x & 31;
    if (node >= N_NODES) return;

    int beg = g_rowptr[node];
    int end = g_rowptr[node + 1];

    if (RESET_CNT && lane == 0) g_cnt[node] = 0;   // state reset for next replay

    float4 acc = make_float4(0.f, 0.f, 0.f, 0.f);
    const uint2* in2 = (const uint2*)in;

    int e = beg;
    for (; e + 4 <= end; e += 4) {
        int2 e0 = g_edge[e],     e1 = g_edge[e + 1];
        int2 e2 = g_edge[e + 2], e3 = g_edge[e + 3];
        uint2 x0 = in2[e0.x * 32 + lane];
        uint2 x1 = in2[e1.x * 32 + lane];
        uint2 x2 = in2[e2.x * 32 + lane];
        uint2 x3 = in2[e3.x * 32 + lane];
        acc = acc_row(acc, x0, __int_as_float(e0.y));
        acc = acc_row(acc, x1, __int_as_float(e1.y));
        acc = acc_row(acc, x2, __int_as_float(e2.y));
        acc = acc_row(acc, x3, __int_as_float(e3.y));
    }
    for (; e < end; e++) {
        int2 ed = g_edge[e];
        acc = acc_row(acc, in2[ed.x * 32 + lane], __int_as_float(ed.y));
    }

    // diag transform: t = acc * w
    float4 w4 = ((const float4*)w)[lane];
    float4 t;
    t.x = acc.x * w4.x; t.y = acc.y * w4.y;
    t.z = acc.z * w4.z; t.w = acc.w * w4.w;

    // LayerNorm via warp reduce
    float sm = t.x + t.y + t.z + t.w;
    float sq = t.x * t.x + t.y * t.y + t.z * t.z + t.w * t.w;
    #pragma unroll
    for (int o = 16; o; o >>= 1) {
        sm += __shfl_xor_sync(0xffffffffu, sm, o);
        sq += __shfl_xor_sync(0xffffffffu, sq, o);
    }
    float mu  = sm * (1.f / D);
    float var = sq * (1.f / D) - mu * mu;
    float rs  = rsqrtf(var + LN_EPS);

    float4 g4 = ((const float4*)gam)[lane];
    float4 b4 = ((const float4*)bet)[lane];
    float4 o4;
    o4.x = fmaf((t.x - mu) * rs, g4.x, b4.x);
    o4.y = fmaf((t.y - mu) * rs, g4.y, b4.y);
    o4.z = fmaf((t.z - mu) * rs, g4.z, b4.z);
    o4.w = fmaf((t.w - mu) * rs, g4.w, b4.w);
    if (RELU) {
        o4.x = fmaxf(o4.x, 0.f); o4.y = fmaxf(o4.y, 0.f);
        o4.z = fmaxf(o4.z, 0.f); o4.w = fmaxf(o4.w, 0.f);
    }

    if (OUT_HALF) {
        __half2 lo = __floats2half2_rn(o4.x, o4.y);
        __half2 hi = __floats2half2_rn(o4.z, o4.w);
        uint2 p;
        p.x = *(unsigned int*)&lo;
        p.y = *(unsigned int*)&hi;
        ((uint2*)out)[node * 32 + lane] = p;
    } else {
        ((float4*)out)[node * 32 + lane] = o4;
    }
}

__global__ void k_layer0(const float* __restrict__ w,
                         const float* __restrict__ gam,
                         const float* __restrict__ bet) {
    agg_node<true, true, true>(g_xh, w, gam, bet, (void*)g_h);
}

__global__ void k_layer1(const float* __restrict__ w,
                         const float* __restrict__ gam,
                         const float* __restrict__ bet,
                         float* __restrict__ out) {
    agg_node<false, false, false>(g_h, w, gam, bet, (void*)out);
}

// ---------------------------------------------------------------
extern "C" void kernel_launch(void* const* d_in, const int* in_sizes, int n_in,
                              void* d_out, int out_size) {
    const float* x     = (const float*)d_in[0];
    const int*   esrc  = (const int*)  d_in[1];
    const int*   edst  = (const int*)  d_in[2];
    const float* eval_ = (const float*)d_in[3];
    const float* w1    = (const float*)d_in[4];
    const float* w2    = (const float*)d_in[5];
    const float* ln1g  = (const float*)d_in[6];
    const float* ln1b  = (const float*)d_in[7];
    const float* ln2g  = (const float*)d_in[8];
    const float* ln2b  = (const float*)d_in[9];
    float* out = (float*)d_out;

    k_cvt_hist<<<1024, 256>>>(x, edst);
    k_scan<<<N_TILES, TILE_THREADS>>>();
    k_scatter<<<(N_EDGES / 4 + 255) / 256, 256>>>(esrc, edst, eval_);

    int blocks = (N_NODES * 32 + 255) / 256;
    k_layer0<<<blocks, 256>>>(w1, ln1g, ln1b);
    k_layer1<<<blocks, 256>>>(w2, ln2g, ln2b, out);
}

// round 9
// speedup vs baseline: 1.0977x; 1.0708x over previous
#include <cuda_runtime.h>
#include <cuda_fp16.h>

#define N_NODES 100000
#define N_EDGES 1600000
#define D       128
#define LN_EPS  1e-5f

// lookback scan config
#define TILE_THREADS 256
#define ITEMS        16
#define SCAN_TILE    (TILE_THREADS * ITEMS)                  // 4096
#define N_TILES      ((N_NODES + SCAN_TILE - 1) / SCAN_TILE) // 25

// ------- scratch (device globals; zero-initialized at load) -------
__device__ int    g_cnt[N_NODES];          // degrees; reset by layer0 epilogue
__device__ int    g_rowptr[N_NODES + 1];   // exclusive prefix; [N] set by scatter
__device__ int    g_cursor[N_NODES];       // scan writes prefix; scatter consumes
__device__ int    g_tstate[N_TILES];       // reset by scatter (post-scan)
__device__ int    g_ticket;                // reset by scatter (post-scan)
__device__ int2   g_edge[N_EDGES];         // (src, val) in CSR order
__device__ __half g_xh[N_NODES * D];       // fp16 copy of x   (25.6 MB)
__device__ __half g_h[N_NODES * D];        // fp16 layer-0 out (25.6 MB)

// ---------------------------------------------------------------
// degree histogram only (atomic results discarded -> REDG no-return)
// ---------------------------------------------------------------
__global__ void k_hist(const int* __restrict__ dst) {
    int tid = blockIdx.x * blockDim.x + threadIdx.x;
    int gsz = gridDim.x * blockDim.x;
    const int4* d4 = (const int4*)dst;
    for (int i = tid; i < N_EDGES / 4; i += gsz) {
        int4 d = d4[i];
        atomicAdd(&g_cnt[d.x], 1);
        atomicAdd(&g_cnt[d.y], 1);
        atomicAdd(&g_cnt[d.z], 1);
        atomicAdd(&g_cnt[d.w], 1);
    }
}

// ---------------------------------------------------------------
// single-pass exclusive scan (decoupled lookback): g_cnt -> g_rowptr
// ALSO writes the same prefix into g_cursor (scatter's atomic base)
// ---------------------------------------------------------------
__global__ void __launch_bounds__(TILE_THREADS) k_scan() {
    __shared__ int sh_warp[TILE_THREADS / 32];
    __shared__ int sh_prev;
    __shared__ int sh_tile;

    int t = threadIdx.x;
    if (t == 0) sh_tile = atomicAdd(&g_ticket, 1);
    __syncthreads();
    int tile = sh_tile;
    int base = tile * SCAN_TILE + t * ITEMS;

    int v[ITEMS];
    #pragma unroll
    for (int i = 0; i < ITEMS; i += 4) {
        int idx = base + i;
        int4 c;
        if (idx + 3 < N_NODES) {
            c = *(const int4*)&g_cnt[idx];
        } else {
            c.x = (idx     < N_NODES) ? g_cnt[idx]     : 0;
            c.y = (idx + 1 < N_NODES) ? g_cnt[idx + 1] : 0;
            c.z = (idx + 2 < N_NODES) ? g_cnt[idx + 2] : 0;
            c.w = (idx + 3 < N_NODES) ? g_cnt[idx + 3] : 0;
        }
        v[i] = c.x; v[i + 1] = c.y; v[i + 2] = c.z; v[i + 3] = c.w;
    }
    #pragma unroll
    for (int i = 1; i < ITEMS; i++) v[i] += v[i - 1];

    int tot = v[ITEMS - 1];
    int lane = t & 31, wid = t >> 5;
    int s = tot;
    #pragma unroll
    for (int o = 1; o < 32; o <<= 1) {
        int n = __shfl_up_sync(0xffffffffu, s, o);
        if (lane >= o) s += n;
    }
    if (lane == 31) sh_warp[wid] = s;
    __syncthreads();
    if (wid == 0) {
        int ws = (lane < TILE_THREADS / 32) ? sh_warp[lane] : 0;
        #pragma unroll
        for (int o = 1; o < TILE_THREADS / 32; o <<= 1) {
            int n = __shfl_up_sync(0xffffffffu, ws, o);
            if (lane >= o) ws += n;
        }
        if (lane < TILE_THREADS / 32) sh_warp[lane] = ws;
    }
    __syncthreads();
    int thr_excl  = (wid > 0 ? sh_warp[wid - 1] : 0) + (s - tot);
    int block_tot = sh_warp[TILE_THREADS / 32 - 1];

    if (t == 0) {
        if (tile == 0) {
            __threadfence();
            atomicExch(&g_tstate[0], (block_tot << 2) | 2);
            sh_prev = 0;
        } else {
            __threadfence();
            atomicExch(&g_tstate[tile], (block_tot << 2) | 1);
            int prev = 0;
            int j = tile - 1;
            while (true) {
                int st = atomicAdd(&g_tstate[j], 0);
                int f = st & 3;
                if (f == 2) { prev += st >> 2; break; }
                if (f == 1) { prev += st >> 2; j--; }
            }
            __threadfence();
            atomicExch(&g_tstate[tile], ((prev + block_tot) << 2) | 2);
            sh_prev = prev;
        }
    }
    __syncthreads();
    int excl = sh_prev + thr_excl;

    #pragma unroll
    for (int i = 0; i < ITEMS; i += 4) {
        int idx = base + i;
        int4 o;
        o.x = excl + (i > 0 ? v[i - 1] : 0);
        o.y = excl + v[i];
        o.z = excl + v[i + 1];
        o.w = excl + v[i + 2];
        if (idx + 3 < N_NODES) {
            *(int4*)&g_rowptr[idx] = o;
            *(int4*)&g_cursor[idx] = o;
        } else {
            if (idx     < N_NODES) { g_rowptr[idx]     = o.x; g_cursor[idx]     = o.x; }
            if (idx + 1 < N_NODES) { g_rowptr[idx + 1] = o.y; g_cursor[idx + 1] = o.y; }
            if (idx + 2 < N_NODES) { g_rowptr[idx + 2] = o.z; g_cursor[idx + 2] = o.z; }
            if (idx + 3 < N_NODES) { g_rowptr[idx + 3] = o.w; g_cursor[idx + 3] = o.w; }
        }
    }
}

// ---------------------------------------------------------------
// scatter (one edge/thread; R6 form) FUSED with fp32->fp16 cvt of x.
// The cvt's DRAM stream hides in the scatter's atomic-latency stalls.
// Also resets scan state for next replay.
// ---------------------------------------------------------------
__global__ void k_scatter_cvt(const int* __restrict__ src,
                              const int* __restrict__ dst,
                              const float* __restrict__ val,
                              const float* __restrict__ x) {
    int e = blockIdx.x * blockDim.x + threadIdx.x;
    int gsz = gridDim.x * blockDim.x;

    if (e < N_TILES) g_tstate[e] = 0;                 // post-scan reset
    if (e == N_TILES)     g_ticket = 0;
    if (e == N_TILES + 1) g_rowptr[N_NODES] = N_EDGES;

    // cvt: grid-stride over 3.2M float4 (2 per thread at this grid size)
    const float4* x4 = (const float4*)x;
    uint2* o2 = (uint2*)g_xh;
    for (int i = e; i < N_NODES * D / 4; i += gsz) {
        float4 v = x4[i];
        __half2 lo = __floats2half2_rn(v.x, v.y);
        __half2 hi = __floats2half2_rn(v.z, v.w);
        uint2 p;
        p.x = *(unsigned int*)&lo;
        p.y = *(unsigned int*)&hi;
        o2[i] = p;
    }

    // scatter: p = atomicAdd(cursor[d]) is the absolute CSR slot
    if (e < N_EDGES) {
        int   d = dst[e];
        int   s = src[e];
        float v = val[e];
        int p = atomicAdd(&g_cursor[d], 1);
        g_edge[p] = make_int2(s, __float_as_int(v));
    }
}

// ---------------------------------------------------------------
// fused gather(fp16)-aggregate(fp32) + diag-scale + LayerNorm (+ReLU)
// one warp per node; lane l owns features [4l, 4l+4)   (R6 form — frozen)
// ---------------------------------------------------------------
__device__ __forceinline__ float4 acc_row(float4 acc, uint2 u, float v) {
    float2 flo = __half22float2(*(__half2*)&u.x);
    float2 fhi = __half22float2(*(__half2*)&u.y);
    acc.x = fmaf(v, flo.x, acc.x);
    acc.y = fmaf(v, flo.y, acc.y);
    acc.z = fmaf(v, fhi.x, acc.z);
    acc.w = fmaf(v, fhi.y, acc.w);
    return acc;
}

template <bool RELU, bool OUT_HALF, bool RESET_CNT>
__device__ __forceinline__ void agg_node(const __half* __restrict__ in,
                                         const float* __restrict__ w,
                                         const float* __restrict__ gam,
                                         const float* __restrict__ bet,
                                         void* __restrict__ out) {
    int node = (blockIdx.x * blockDim.x + threadIdx.x) >> 5;
    int lane = threadIdx.x & 31;
    if (node >= N_NODES) return;

    int beg = g_rowptr[node];
    int end = g_rowptr[node + 1];

    if (RESET_CNT && lane == 0) g_cnt[node] = 0;   // state reset for next replay

    float4 acc = make_float4(0.f, 0.f, 0.f, 0.f);
    const uint2* in2 = (const uint2*)in;

    int e = beg;
    for (; e + 4 <= end; e += 4) {
        int2 e0 = g_edge[e],     e1 = g_edge[e + 1];
        int2 e2 = g_edge[e + 2], e3 = g_edge[e + 3];
        uint2 x0 = in2[e0.x * 32 + lane];
        uint2 x1 = in2[e1.x * 32 + lane];
        uint2 x2 = in2[e2.x * 32 + lane];
        uint2 x3 = in2[e3.x * 32 + lane];
        acc = acc_row(acc, x0, __int_as_float(e0.y));
        acc = acc_row(acc, x1, __int_as_float(e1.y));
        acc = acc_row(acc, x2, __int_as_float(e2.y));
        acc = acc_row(acc, x3, __int_as_float(e3.y));
    }
    for (; e < end; e++) {
        int2 ed = g_edge[e];
        acc = acc_row(acc, in2[ed.x * 32 + lane], __int_as_float(ed.y));
    }

    // diag transform: t = acc * w
    float4 w4 = ((const float4*)w)[lane];
    float4 t;
    t.x = acc.x * w4.x; t.y = acc.y * w4.y;
    t.z = acc.z * w4.z; t.w = acc.w * w4.w;

    // LayerNorm via warp reduce
    float sm = t.x + t.y + t.z + t.w;
    float sq = t.x * t.x + t.y * t.y + t.z * t.z + t.w * t.w;
    #pragma unroll
    for (int o = 16; o; o >>= 1) {
        sm += __shfl_xor_sync(0xffffffffu, sm, o);
        sq += __shfl_xor_sync(0xffffffffu, sq, o);
    }
    float mu  = sm * (1.f / D);
    float var = sq * (1.f / D) - mu * mu;
    float rs  = rsqrtf(var + LN_EPS);

    float4 g4 = ((const float4*)gam)[lane];
    float4 b4 = ((const float4*)bet)[lane];
    float4 o4;
    o4.x = fmaf((t.x - mu) * rs, g4.x, b4.x);
    o4.y = fmaf((t.y - mu) * rs, g4.y, b4.y);
    o4.z = fmaf((t.z - mu) * rs, g4.z, b4.z);
    o4.w = fmaf((t.w - mu) * rs, g4.w, b4.w);
    if (RELU) {
        o4.x = fmaxf(o4.x, 0.f); o4.y = fmaxf(o4.y, 0.f);
        o4.z = fmaxf(o4.z, 0.f); o4.w = fmaxf(o4.w, 0.f);
    }

    if (OUT_HALF) {
        __half2 lo = __floats2half2_rn(o4.x, o4.y);
        __half2 hi = __floats2half2_rn(o4.z, o4.w);
        uint2 p;
        p.x = *(unsigned int*)&lo;
        p.y = *(unsigned int*)&hi;
        ((uint2*)out)[node * 32 + lane] = p;
    } else {
        ((float4*)out)[node * 32 + lane] = o4;
    }
}

__global__ void k_layer0(const float* __restrict__ w,
                         const float* __restrict__ gam,
                         const float* __restrict__ bet) {
    agg_node<true, true, true>(g_xh, w, gam, bet, (void*)g_h);
}

__global__ void k_layer1(const float* __restrict__ w,
                         const float* __restrict__ gam,
                         const float* __restrict__ bet,
                         float* __restrict__ out) {
    agg_node<false, false, false>(g_h, w, gam, bet, (void*)out);
}

// ---------------------------------------------------------------
extern "C" void kernel_launch(void* const* d_in, const int* in_sizes, int n_in,
                              void* d_out, int out_size) {
    const float* x     = (const float*)d_in[0];
    const int*   esrc  = (const int*)  d_in[1];
    const int*   edst  = (const int*)  d_in[2];
    const float* eval_ = (const float*)d_in[3];
    const float* w1    = (const float*)d_in[4];
    const float* w2    = (const float*)d_in[5];
    const float* ln1g  = (const float*)d_in[6];
    const float* ln1b  = (const float*)d_in[7];
    const float* ln2g  = (const float*)d_in[8];
    const float* ln2b  = (const float*)d_in[9];
    float* out = (float*)d_out;

    k_hist<<<(N_EDGES / 4 + 255) / 256, 256>>>(edst);
    k_scan<<<N_TILES, TILE_THREADS>>>();
    k_scatter_cvt<<<(N_EDGES + 255) / 256, 256>>>(esrc, edst, eval_, x);

    int blocks = (N_NODES * 32 + 255) / 256;
    k_layer0<<<blocks, 256>>>(w1, ln1g, ln1b);
    k_layer1<<<blocks, 256>>>(w2, ln2g, ln2b, out);
}

// round 10
// speedup vs baseline: 1.1178x; 1.0184x over previous
#include <cuda_runtime.h>
#include <cuda_fp16.h>

#define N_NODES 100000
#define N_EDGES 1600000
#define D       128
#define LN_EPS  1e-5f

// lookback scan config
#define TILE_THREADS 256
#define ITEMS        16
#define SCAN_TILE    (TILE_THREADS * ITEMS)                  // 4096
#define N_TILES      ((N_NODES + SCAN_TILE - 1) / SCAN_TILE) // 25

// ------- scratch (device globals; zero-initialized at load) -------
__device__ int    g_cnt[N_NODES];          // degrees; reset by layer0 epilogue
__device__ int    g_rowptr[N_NODES + 1];   // exclusive prefix; [N] set by scatter
__device__ int    g_cursor[N_NODES];       // scan writes prefix; scatter consumes
__device__ int    g_tstate[N_TILES];       // reset by scatter (post-scan)
__device__ int    g_ticket;                // reset by scatter (post-scan)
__device__ int2   g_edge[N_EDGES];         // (src, val as duplicated half2)
__device__ __half g_xh[N_NODES * D];       // fp16 copy of x   (25.6 MB)
__device__ __half g_h[N_NODES * D];        // fp16 layer-0 out (25.6 MB)

// ---------------------------------------------------------------
// degree histogram only (atomic results discarded -> REDG no-return)
// ---------------------------------------------------------------
__global__ void k_hist(const int* __restrict__ dst) {
    int tid = blockIdx.x * blockDim.x + threadIdx.x;
    int gsz = gridDim.x * blockDim.x;
    const int4* d4 = (const int4*)dst;
    for (int i = tid; i < N_EDGES / 4; i += gsz) {
        int4 d = d4[i];
        atomicAdd(&g_cnt[d.x], 1);
        atomicAdd(&g_cnt[d.y], 1);
        atomicAdd(&g_cnt[d.z], 1);
        atomicAdd(&g_cnt[d.w], 1);
    }
}

// ---------------------------------------------------------------
// single-pass exclusive scan (decoupled lookback): g_cnt -> g_rowptr
// ALSO writes the same prefix into g_cursor (scatter's atomic base)
// ---------------------------------------------------------------
__global__ void __launch_bounds__(TILE_THREADS) k_scan() {
    __shared__ int sh_warp[TILE_THREADS / 32];
    __shared__ int sh_prev;
    __shared__ int sh_tile;

    int t = threadIdx.x;
    if (t == 0) sh_tile = atomicAdd(&g_ticket, 1);
    __syncthreads();
    int tile = sh_tile;
    int base = tile * SCAN_TILE + t * ITEMS;

    int v[ITEMS];
    #pragma unroll
    for (int i = 0; i < ITEMS; i += 4) {
        int idx = base + i;
        int4 c;
        if (idx + 3 < N_NODES) {
            c = *(const int4*)&g_cnt[idx];
        } else {
            c.x = (idx     < N_NODES) ? g_cnt[idx]     : 0;
            c.y = (idx + 1 < N_NODES) ? g_cnt[idx + 1] : 0;
            c.z = (idx + 2 < N_NODES) ? g_cnt[idx + 2] : 0;
            c.w = (idx + 3 < N_NODES) ? g_cnt[idx + 3] : 0;
        }
        v[i] = c.x; v[i + 1] = c.y; v[i + 2] = c.z; v[i + 3] = c.w;
    }
    #pragma unroll
    for (int i = 1; i < ITEMS; i++) v[i] += v[i - 1];

    int tot = v[ITEMS - 1];
    int lane = t & 31, wid = t >> 5;
    int s = tot;
    #pragma unroll
    for (int o = 1; o < 32; o <<= 1) {
        int n = __shfl_up_sync(0xffffffffu, s, o);
        if (lane >= o) s += n;
    }
    if (lane == 31) sh_warp[wid] = s;
    __syncthreads();
    if (wid == 0) {
        int ws = (lane < TILE_THREADS / 32) ? sh_warp[lane] : 0;
        #pragma unroll
        for (int o = 1; o < TILE_THREADS / 32; o <<= 1) {
            int n = __shfl_up_sync(0xffffffffu, ws, o);
            if (lane >= o) ws += n;
        }
        if (lane < TILE_THREADS / 32) sh_warp[lane] = ws;
    }
    __syncthreads();
    int thr_excl  = (wid > 0 ? sh_warp[wid - 1] : 0) + (s - tot);
    int block_tot = sh_warp[TILE_THREADS / 32 - 1];

    if (t == 0) {
        if (tile == 0) {
            __threadfence();
            atomicExch(&g_tstate[0], (block_tot << 2) | 2);
            sh_prev = 0;
        } else {
            __threadfence();
            atomicExch(&g_tstate[tile], (block_tot << 2) | 1);
            int prev = 0;
            int j = tile - 1;
            while (true) {
                int st = atomicAdd(&g_tstate[j], 0);
                int f = st & 3;
                if (f == 2) { prev += st >> 2; break; }
                if (f == 1) { prev += st >> 2; j--; }
            }
            __threadfence();
            atomicExch(&g_tstate[tile], ((prev + block_tot) << 2) | 2);
            sh_prev = prev;
        }
    }
    __syncthreads();
    int excl = sh_prev + thr_excl;

    #pragma unroll
    for (int i = 0; i < ITEMS; i += 4) {
        int idx = base + i;
        int4 o;
        o.x = excl + (i > 0 ? v[i - 1] : 0);
        o.y = excl + v[i];
        o.z = excl + v[i + 1];
        o.w = excl + v[i + 2];
        if (idx + 3 < N_NODES) {
            *(int4*)&g_rowptr[idx] = o;
            *(int4*)&g_cursor[idx] = o;
        } else {
            if (idx     < N_NODES) { g_rowptr[idx]     = o.x; g_cursor[idx]     = o.x; }
            if (idx + 1 < N_NODES) { g_rowptr[idx + 1] = o.y; g_cursor[idx + 1] = o.y; }
            if (idx + 2 < N_NODES) { g_rowptr[idx + 2] = o.z; g_cursor[idx + 2] = o.z; }
            if (idx + 3 < N_NODES) { g_rowptr[idx + 3] = o.w; g_cursor[idx + 3] = o.w; }
        }
    }
}

// ---------------------------------------------------------------
// scatter (one edge/thread) FUSED with fp32->fp16 cvt of x.
// Stores val as DUPLICATED half2 (converted here, in the latency shadow).
// Also resets scan state for next replay.
// ---------------------------------------------------------------
__global__ void k_scatter_cvt(const int* __restrict__ src,
                              const int* __restrict__ dst,
                              const float* __restrict__ val,
                              const float* __restrict__ x) {
    int e = blockIdx.x * blockDim.x + threadIdx.x;
    int gsz = gridDim.x * blockDim.x;

    if (e < N_TILES) g_tstate[e] = 0;                 // post-scan reset
    if (e == N_TILES)     g_ticket = 0;
    if (e == N_TILES + 1) g_rowptr[N_NODES] = N_EDGES;

    // cvt: grid-stride over 3.2M float4 (2 per thread at this grid size)
    const float4* x4 = (const float4*)x;
    uint2* o2 = (uint2*)g_xh;
    for (int i = e; i < N_NODES * D / 4; i += gsz) {
        float4 v = x4[i];
        __half2 lo = __floats2half2_rn(v.x, v.y);
        __half2 hi = __floats2half2_rn(v.z, v.w);
        uint2 p;
        p.x = *(unsigned int*)&lo;
        p.y = *(unsigned int*)&hi;
        o2[i] = p;
    }

    // scatter: p = atomicAdd(cursor[d]) is the absolute CSR slot
    if (e < N_EDGES) {
        int   d = dst[e];
        int   s = src[e];
        float v = val[e];
        __half2 vh = __float2half2_rn(v);           // duplicated half2
        int p = atomicAdd(&g_cursor[d], 1);
        g_edge[p] = make_int2(s, (int)*(unsigned int*)&vh);
    }
}

// ---------------------------------------------------------------
// fused gather(fp16)-aggregate + diag-scale + LayerNorm (+ReLU)
// one warp per node; lane l owns features [4l, 4l+4).
// Edge PAIRS combined in fp16 (HMUL2/HFMA2), partials upconverted
// once per pair, accumulated in fp32  -> F2F count halved.
// ---------------------------------------------------------------
__device__ __forceinline__ __half2 as_h2(unsigned int u) { return *(__half2*)&u; }

template <bool RELU, bool OUT_HALF, bool RESET_CNT>
__device__ __forceinline__ void agg_node(const __half* __restrict__ in,
                                         const float* __restrict__ w,
                                         const float* __restrict__ gam,
                                         const float* __restrict__ bet,
                                         void* __restrict__ out) {
    int node = (blockIdx.x * blockDim.x + threadIdx.x) >> 5;
    int lane = threadIdx.x & 31;
    if (node >= N_NODES) return;

    int beg = g_rowptr[node];
    int end = g_rowptr[node + 1];

    if (RESET_CNT && lane == 0) g_cnt[node] = 0;   // state reset for next replay

    float4 acc = make_float4(0.f, 0.f, 0.f, 0.f);
    const uint2* in2 = (const uint2*)in;

    int e = beg;
    for (; e + 4 <= end; e += 4) {
        int2 e0 = g_edge[e],     e1 = g_edge[e + 1];
        int2 e2 = g_edge[e + 2], e3 = g_edge[e + 3];
        uint2 x0 = in2[e0.x * 32 + lane];
        uint2 x1 = in2[e1.x * 32 + lane];
        uint2 x2 = in2[e2.x * 32 + lane];
        uint2 x3 = in2[e3.x * 32 + lane];
        __half2 v0 = as_h2((unsigned int)e0.y), v1 = as_h2((unsigned int)e1.y);
        __half2 v2 = as_h2((unsigned int)e2.y), v3 = as_h2((unsigned int)e3.y);

        // pair (e0, e1): fp16 2-term partials
        __half2 q0 = __hmul2(as_h2(x0.x), v0);
        q0 = __hfma2(as_h2(x1.x), v1, q0);
        __half2 q1 = __hmul2(as_h2(x0.y), v0);
        q1 = __hfma2(as_h2(x1.y), v1, q1);
        // pair (e2, e3)
        __half2 r0 = __hmul2(as_h2(x2.x), v2);
        r0 = __hfma2(as_h2(x3.x), v3, r0);
        __half2 r1 = __hmul2(as_h2(x2.y), v2);
        r1 = __hfma2(as_h2(x3.y), v3, r1);

        float2 f;
        f = __half22float2(q0); acc.x += f.x; acc.y += f.y;
        f = __half22float2(q1); acc.z += f.x; acc.w += f.y;
        f = __half22float2(r0); acc.x += f.x; acc.y += f.y;
        f = __half22float2(r1); acc.z += f.x; acc.w += f.y;
    }
    // pair tail
    if (e + 2 <= end) {
        int2 e0 = g_edge[e], e1 = g_edge[e + 1];
        uint2 x0 = in2[e0.x * 32 + lane];
        uint2 x1 = in2[e1.x * 32 + lane];
        __half2 v0 = as_h2((unsigned int)e0.y), v1 = as_h2((unsigned int)e1.y);
        __half2 q0 = __hmul2(as_h2(x0.x), v0);
        q0 = __hfma2(as_h2(x1.x), v1, q0);
        __half2 q1 = __hmul2(as_h2(x0.y), v0);
        q1 = __hfma2(as_h2(x1.y), v1, q1);
        float2 f;
        f = __half22float2(q0); acc.x += f.x; acc.y += f.y;
        f = __half22float2(q1); acc.z += f.x; acc.w += f.y;
        e += 2;
    }
    // single tail
    if (e < end) {
        int2 ed = g_edge[e];
        uint2 x0 = in2[ed.x * 32 + lane];
        __half2 v = as_h2((unsigned int)ed.y);
        __half2 q0 = __hmul2(as_h2(x0.x), v);
        __half2 q1 = __hmul2(as_h2(x0.y), v);
        float2 f;
        f = __half22float2(q0); acc.x += f.x; acc.y += f.y;
        f = __half22float2(q1); acc.z += f.x; acc.w += f.y;
    }

    // diag transform: t = acc * w
    float4 w4 = ((const float4*)w)[lane];
    float4 t;
    t.x = acc.x * w4.x; t.y = acc.y * w4.y;
    t.z = acc.z * w4.z; t.w = acc.w * w4.w;

    // LayerNorm via warp reduce
    float sm = t.x + t.y + t.z + t.w;
    float sq = t.x * t.x + t.y * t.y + t.z * t.z + t.w * t.w;
    #pragma unroll
    for (int o = 16; o; o >>= 1) {
        sm += __shfl_xor_sync(0xffffffffu, sm, o);
        sq += __shfl_xor_sync(0xffffffffu, sq, o);
    }
    float mu  = sm * (1.f / D);
    float var = sq * (1.f / D) - mu * mu;
    float rs  = rsqrtf(var + LN_EPS);

    float4 g4 = ((const float4*)gam)[lane];
    float4 b4 = ((const float4*)bet)[lane];
    float4 o4;
    o4.x = fmaf((t.x - mu) * rs, g4.x, b4.x);
    o4.y = fmaf((t.y - mu) * rs, g4.y, b4.y);
    o4.z = fmaf((t.z - mu) * rs, g4.z, b4.z);
    o4.w = fmaf((t.w - mu) * rs, g4.w, b4.w);
    if (RELU) {
        o4.x = fmaxf(o4.x, 0.f); o4.y = fmaxf(o4.y, 0.f);
        o4.z = fmaxf(o4.z, 0.f); o4.w = fmaxf(o4.w, 0.f);
    }

    if (OUT_HALF) {
        __half2 lo = __floats2half2_rn(o4.x, o4.y);
        __half2 hi = __floats2half2_rn(o4.z, o4.w);
        uint2 p;
        p.x = *(unsigned int*)&lo;
        p.y = *(unsigned int*)&hi;
        ((uint2*)out)[node * 32 + lane] = p;
    } else {
        ((float4*)out)[node * 32 + lane] = o4;
    }
}

__global__ void k_layer0(const float* __restrict__ w,
                         const float* __restrict__ gam,
                         const float* __restrict__ bet) {
    agg_node<true, true, true>(g_xh, w, gam, bet, (void*)g_h);
}

__global__ void k_layer1(const float* __restrict__ w,
                         const float* __restrict__ gam,
                         const float* __restrict__ bet,
                         float* __restrict__ out) {
    agg_node<false, false, false>(g_h, w, gam, bet, (void*)out);
}

// ---------------------------------------------------------------
extern "C" void kernel_launch(void* const* d_in, const int* in_sizes, int n_in,
                              void* d_out, int out_size) {
    const float* x     = (const float*)d_in[0];
    const int*   esrc  = (const int*)  d_in[1];
    const int*   edst  = (const int*)  d_in[2];
    const float* eval_ = (const float*)d_in[3];
    const float* w1    = (const float*)d_in[4];
    const float* w2    = (const float*)d_in[5];
    const float* ln1g  = (const float*)d_in[6];
    const float* ln1b  = (const float*)d_in[7];
    const float* ln2g  = (const float*)d_in[8];
    const float* ln2b  = (const float*)d_in[9];
    float* out = (float*)d_out;

    k_hist<<<(N_EDGES / 4 + 255) / 256, 256>>>(edst);
    k_scan<<<N_TILES, TILE_THREADS>>>();
    k_scatter_cvt<<<(N_EDGES + 255) / 256, 256>>>(esrc, edst, eval_, x);

    int blocks = (N_NODES * 32 + 255) / 256;
    k_layer0<<<blocks, 256>>>(w1, ln1g, ln1b);
    k_layer1<<<blocks, 256>>>(w2, ln2g, ln2b, out);
}